// round 1
// baseline (speedup 1.0000x reference)
#include <cuda_runtime.h>
#include <cuda_bf16.h>

// Problem constants (fixed shapes for MetaGAT_34926674051560)
#define NN   5000
#define EE   80000
#define HH   32
#define BB   16
#define FEAT 47
#define FPAD 48   // padded feature row for float4 loads

// ---------------- device scratch (no allocations allowed) ----------------
__device__ int   g_count [NN];
__device__ int   g_rowptr[NN + 1];
__device__ int   g_cursor[NN];
__device__ int   g_elist [EE];
__device__ float g_c     [2 * EE];      // per-edge (c0, c1) post-sigmoid
__device__ float g_featp [NN * FPAD];   // padded feature copy

__device__ __forceinline__ float fsigmoid(float x) {
    return __fdividef(1.0f, 1.0f + __expf(-x));
}

// ---------------- kernel 0: zero per-node counters ----------------
__global__ void k_zero() {
    int i = blockIdx.x * blockDim.x + threadIdx.x;
    if (i < NN) g_count[i] = 0;
}

// ---------------- kernel 1: pad features to 48 floats/row ----------------
__global__ void k_padfeat(const float* __restrict__ feature) {
    int i = blockIdx.x * blockDim.x + threadIdx.x;
    if (i < NN * FPAD) {
        int n = i / FPAD, c = i % FPAD;
        g_featp[i] = (c < FEAT) ? feature[n * FEAT + c] : 0.0f;
    }
}

// ---------------- kernel 2: count edges per dst ----------------
__global__ void k_count(const int* __restrict__ dst) {
    int e = blockIdx.x * blockDim.x + threadIdx.x;
    if (e < EE) atomicAdd(&g_count[dst[e]], 1);
}

// ---------------- kernel 3: exclusive scan (single block) ----------------
__global__ void k_scan() {
    __shared__ int sm[1024];
    int tid  = threadIdx.x;
    int base = tid * 5;
    int loc[5];
    int run = 0;
#pragma unroll
    for (int t = 0; t < 5; ++t) {
        loc[t] = run;
        int idx = base + t;
        run += (idx < NN) ? g_count[idx] : 0;
    }
    sm[tid] = run;
    __syncthreads();
    for (int off = 1; off < 1024; off <<= 1) {
        int v = (tid >= off) ? sm[tid - off] : 0;
        __syncthreads();
        sm[tid] += v;
        __syncthreads();
    }
    int excl = (tid > 0) ? sm[tid - 1] : 0;
#pragma unroll
    for (int t = 0; t < 5; ++t) {
        int idx = base + t;
        if (idx < NN) {
            g_rowptr[idx] = excl + loc[t];
            g_cursor[idx] = excl + loc[t];
        }
    }
    if (tid == 1023) g_rowptr[NN] = sm[1023];
}

// ---------------- kernel 4: fill CSR edge list ----------------
__global__ void k_fill(const int* __restrict__ dst) {
    int e = blockIdx.x * blockDim.x + threadIdx.x;
    if (e < EE) {
        int idx = atomicAdd(&g_cursor[dst[e]], 1);
        g_elist[idx] = e;
    }
}

// ---------------- kernel 5: per-edge tiny MLP -> (c0, c1) ----------------
__global__ void __launch_bounds__(256) k_cmlp(
    const float* __restrict__ dist,
    const float* __restrict__ w1, const float* __restrict__ b1,
    const float* __restrict__ w2, const float* __restrict__ b2,
    const int* __restrict__ src, const int* __restrict__ dst)
{
    __shared__ float w1s[96 * 16];
    __shared__ float b1s[16];
    __shared__ float w2s[32];
    __shared__ float b2s[2];
    int tid = threadIdx.x;
    for (int i = tid; i < 96 * 16; i += 256) w1s[i] = w1[i];
    if (tid < 16) b1s[tid] = b1[tid];
    if (tid < 32) w2s[tid] = w2[tid];
    if (tid < 2)  b2s[tid] = b2[tid];
    __syncthreads();

    int e = blockIdx.x * 256 + tid;
    if (e >= EE) return;
    int s = src[e], d = dst[e];

    float h1[16];
#pragma unroll
    for (int j = 0; j < 16; ++j) h1[j] = b1s[j];

    const float4* fs4 = reinterpret_cast<const float4*>(g_featp + s * FPAD);
    const float4* fd4 = reinterpret_cast<const float4*>(g_featp + d * FPAD);

    // feature[src] part: rows 0..46 of w1 (pad element has f==0, safe)
#pragma unroll
    for (int q = 0; q < 12; ++q) {
        float4 f = fs4[q];
        int i0 = q * 4;
#pragma unroll
        for (int j = 0; j < 16; ++j) {
            h1[j] = fmaf(f.x, w1s[(i0 + 0) * 16 + j], h1[j]);
            h1[j] = fmaf(f.y, w1s[(i0 + 1) * 16 + j], h1[j]);
            h1[j] = fmaf(f.z, w1s[(i0 + 2) * 16 + j], h1[j]);
            h1[j] = fmaf(f.w, w1s[(i0 + 3) * 16 + j], h1[j]);
        }
    }
    // feature[dst] part: rows 47..93 (pad element f==0 -> row 94 unused, safe)
#pragma unroll
    for (int q = 0; q < 12; ++q) {
        float4 f = fd4[q];
        int i0 = 47 + q * 4;
#pragma unroll
        for (int j = 0; j < 16; ++j) {
            h1[j] = fmaf(f.x, w1s[(i0 + 0) * 16 + j], h1[j]);
            h1[j] = fmaf(f.y, w1s[(i0 + 1) * 16 + j], h1[j]);
            h1[j] = fmaf(f.z, w1s[(i0 + 2) * 16 + j], h1[j]);
            h1[j] = fmaf(f.w, w1s[(i0 + 3) * 16 + j], h1[j]);
        }
    }
    // dist part: rows 94, 95
    float d0 = dist[2 * e], d1 = dist[2 * e + 1];
#pragma unroll
    for (int j = 0; j < 16; ++j) {
        h1[j] = fmaf(d0, w1s[94 * 16 + j], h1[j]);
        h1[j] = fmaf(d1, w1s[95 * 16 + j], h1[j]);
        h1[j] = fsigmoid(h1[j]);
    }
    float c0 = b2s[0], c1 = b2s[1];
#pragma unroll
    for (int j = 0; j < 16; ++j) {
        c0 = fmaf(h1[j], w2s[2 * j],     c0);
        c1 = fmaf(h1[j], w2s[2 * j + 1], c1);
    }
    g_c[2 * e]     = fsigmoid(c0);
    g_c[2 * e + 1] = fsigmoid(c1);
}

// ---------------- kernel 6: main gather kernel (1 CTA per dst node) ------
// 128 threads: thread = (bq = tid>>5 in [0,4), h = tid&31).
// Thread owns outputs (b, h) for b = bq*4 + i, i in [0,4).
#define WT_STRIDE 68
__global__ void __launch_bounds__(128) k_main(
    const float* __restrict__ state,
    const float* __restrict__ w3, const float* __restrict__ b3,
    const float* __restrict__ weight,
    const int* __restrict__ src,
    float* __restrict__ out)
{
    const int n   = blockIdx.x;
    const int tid = threadIdx.x;
    const int h   = tid & 31;
    const int bq  = tid >> 5;   // warp id, 0..3

    __shared__ float w3a[2048], w3b[2048], b3s[2048];
    __shared__ float Wt[32 * WT_STRIDE];   // W transposed: Wt[h][k]
    __shared__ float sb[16 * 64];          // s[b][k]: k<32 = state[src], k>=32 = state[n]

    // load w3 rows + b3 into smem
    for (int i = tid; i < 2048; i += 128) {
        w3a[i] = w3[i];
        w3b[i] = w3[2048 + i];
        b3s[i] = b3[i];
    }
    // load state[n] into sb high half (k = 32..63). One float4 per thread.
    {
        int idx = tid * 4;            // 0..508
        int b   = idx >> 5;
        int hh  = idx & 31;
        float4 v = *reinterpret_cast<const float4*>(state + n * 512 + idx);
        *reinterpret_cast<float4*>(&sb[b * 64 + 32 + hh]) = v;
    }
    __syncthreads();

    const int rs = g_rowptr[n];
    const int re = g_rowptr[n + 1];

    float den[4] = {0.f, 0.f, 0.f, 0.f};
    float num[4] = {0.f, 0.f, 0.f, 0.f};

    for (int ei = rs; ei < re; ++ei) {
        int   e  = g_elist[ei];
        float c0 = g_c[2 * e];
        float c1 = g_c[2 * e + 1];
        int   sn = src[e];

        // load state[src] into sb low half (k = 0..31)
        {
            int idx = tid * 4;
            int b   = idx >> 5;
            int hh  = idx & 31;
            float4 v = *reinterpret_cast<const float4*>(state + sn * 512 + idx);
            *reinterpret_cast<float4*>(&sb[b * 64 + hh]) = v;
        }
        // regenerate W^T into smem: thread handles k = bq*16 .. bq*16+15, col h
        {
            float wtmp[16];
#pragma unroll
            for (int kk = 0; kk < 16; ++kk) {
                int k = bq * 16 + kk;
                int j = k * 32 + h;
                float x = fmaf(c0, w3a[j], fmaf(c1, w3b[j], b3s[j]));
                wtmp[kk] = fsigmoid(x);
            }
#pragma unroll
            for (int q = 0; q < 4; ++q) {
                *reinterpret_cast<float4*>(&Wt[h * WT_STRIDE + bq * 16 + q * 4]) =
                    make_float4(wtmp[q * 4], wtmp[q * 4 + 1], wtmp[q * 4 + 2], wtmp[q * 4 + 3]);
            }
        }
        __syncthreads();

        // einsum: alpha[b][h] = sum_k s[b][k] * Wt[h][k], 4 b per thread
        float acc[4] = {0.f, 0.f, 0.f, 0.f};
#pragma unroll
        for (int kc = 0; kc < 16; ++kc) {
            float4 w = *reinterpret_cast<const float4*>(&Wt[h * WT_STRIDE + kc * 4]);
#pragma unroll
            for (int i = 0; i < 4; ++i) {
                int b = bq * 4 + i;
                float4 sv = *reinterpret_cast<const float4*>(&sb[b * 64 + kc * 4]);
                acc[i] = fmaf(sv.x, w.x, acc[i]);
                acc[i] = fmaf(sv.y, w.y, acc[i]);
                acc[i] = fmaf(sv.z, w.z, acc[i]);
                acc[i] = fmaf(sv.w, w.w, acc[i]);
            }
        }
        // leaky_relu, exp, accumulate den/num
#pragma unroll
        for (int i = 0; i < 4; ++i) {
            int b = bq * 4 + i;
            float a = acc[i];
            a = (a > 0.f) ? a : 0.01f * a;
            float ex = __expf(a);
            den[i] += ex;
            num[i] = fmaf(ex, sb[b * 64 + h], num[i]);   // ex * state[src][b][h]
        }
        __syncthreads();  // protect sb/Wt before next edge overwrites
    }

    float sigw = fsigmoid(weight[0]);
#pragma unroll
    for (int i = 0; i < 4; ++i) {
        int b = bq * 4 + i;
        float d = (den[i] > 0.f) ? den[i] : 1.f;
        float v = __fdividef(num[i], d) * sigw;
        out[n * 512 + b * 32 + h] = (v > 0.f) ? v : 0.f;
    }
}

// ---------------- launch ----------------
extern "C" void kernel_launch(void* const* d_in, const int* in_sizes, int n_in,
                              void* d_out, int out_size)
{
    const float* state   = (const float*)d_in[0];
    const float* feature = (const float*)d_in[1];
    const float* dist    = (const float*)d_in[2];
    const float* w1      = (const float*)d_in[3];
    const float* b1      = (const float*)d_in[4];
    const float* w2      = (const float*)d_in[5];
    const float* b2      = (const float*)d_in[6];
    const float* w3      = (const float*)d_in[7];
    const float* b3      = (const float*)d_in[8];
    const float* weight  = (const float*)d_in[9];
    const int*   src     = (const int*)d_in[10];
    const int*   dst     = (const int*)d_in[11];
    float* out = (float*)d_out;

    k_zero   <<<(NN + 255) / 256, 256>>>();
    k_padfeat<<<(NN * FPAD + 255) / 256, 256>>>(feature);
    k_count  <<<(EE + 255) / 256, 256>>>(dst);
    k_scan   <<<1, 1024>>>();
    k_fill   <<<(EE + 255) / 256, 256>>>(dst);
    k_cmlp   <<<(EE + 255) / 256, 256>>>(dist, w1, b1, w2, b2, src, dst);
    k_main   <<<NN, 128>>>(state, w3, b3, weight, src, out);
}

// round 2
// speedup vs baseline: 1.2006x; 1.2006x over previous
#include <cuda_runtime.h>
#include <cstdint>

// Problem constants (fixed shapes for MetaGAT_34926674051560)
#define NN   5000
#define EE   80000
#define FEAT 47
#define FPAD 48
#define WT_STRIDE 68   // floats per Wt row (64 used + pad -> conflict-free, 16B-aligned)

using ull = unsigned long long;

// ---------------- device scratch ----------------
__device__ int   g_count [NN];
__device__ int   g_rowptr[NN + 1];
__device__ int   g_cursor[NN];
__device__ int   g_elist [EE];
__device__ float g_c     [2 * EE];
__device__ float g_featp [NN * FPAD];

__device__ __forceinline__ float fsigmoid(float x) {
    return __fdividef(1.0f, 1.0f + __expf(-x));
}
__device__ __forceinline__ ull pk(float lo, float hi) {
    ull r; asm("mov.b64 %0, {%1, %2};" : "=l"(r) : "f"(lo), "f"(hi)); return r;
}
__device__ __forceinline__ void upk(float& lo, float& hi, ull v) {
    asm("mov.b64 {%0, %1}, %2;" : "=f"(lo), "=f"(hi) : "l"(v));
}
__device__ __forceinline__ void ffma2(ull& acc, ull a, ull b) {
    asm("fma.rn.f32x2 %0, %1, %2, %0;" : "+l"(acc) : "l"(a), "l"(b));
}
__device__ __forceinline__ void lds2(ull& a, ull& b, uint32_t addr) {
    asm volatile("ld.shared.v2.b64 {%0, %1}, [%2];" : "=l"(a), "=l"(b) : "r"(addr));
}

// ---------------- kernel: zero counters + pad features (fused) ----------------
__global__ void k_prep(const float* __restrict__ feature) {
    int i = blockIdx.x * blockDim.x + threadIdx.x;
    if (i < NN) g_count[i] = 0;
    if (i < NN * FPAD) {
        int n = i / FPAD, c = i % FPAD;
        g_featp[i] = (c < FEAT) ? feature[n * FEAT + c] : 0.0f;
    }
}

// ---------------- kernel: count edges per dst ----------------
__global__ void k_count(const int* __restrict__ dst) {
    int e = blockIdx.x * blockDim.x + threadIdx.x;
    if (e < EE) atomicAdd(&g_count[dst[e]], 1);
}

// ---------------- kernel: exclusive scan (shfl-based, 1 block) ----------------
__global__ void k_scan() {
    __shared__ int wtot[32];
    int tid = threadIdx.x, lane = tid & 31, wid = tid >> 5;
    int base = tid * 5;
    int loc[5];
    int run = 0;
#pragma unroll
    for (int t = 0; t < 5; ++t) {
        loc[t] = run;
        int idx = base + t;
        run += (idx < NN) ? g_count[idx] : 0;
    }
    int own = run;
    int inc = run;
#pragma unroll
    for (int off = 1; off < 32; off <<= 1) {
        int v = __shfl_up_sync(0xffffffffu, inc, off);
        if (lane >= off) inc += v;
    }
    if (lane == 31) wtot[wid] = inc;
    __syncthreads();
    if (wid == 0) {
        int v = wtot[lane];
        int s = v;
#pragma unroll
        for (int off = 1; off < 32; off <<= 1) {
            int u = __shfl_up_sync(0xffffffffu, s, off);
            if (lane >= off) s += u;
        }
        wtot[lane] = s - v;   // exclusive warp offsets
    }
    __syncthreads();
    int excl = wtot[wid] + inc - own;
#pragma unroll
    for (int t = 0; t < 5; ++t) {
        int idx = base + t;
        if (idx < NN) {
            g_rowptr[idx] = excl + loc[t];
            g_cursor[idx] = excl + loc[t];
        }
    }
    if (tid == 1023) g_rowptr[NN] = excl + own;
}

// ---------------- kernel: fill CSR edge list ----------------
__global__ void k_fill(const int* __restrict__ dst) {
    int e = blockIdx.x * blockDim.x + threadIdx.x;
    if (e < EE) {
        int idx = atomicAdd(&g_cursor[dst[e]], 1);
        g_elist[idx] = e;
    }
}

// ---------------- kernel: per-edge tiny MLP -> (c0, c1) ----------------
__global__ void __launch_bounds__(256) k_cmlp(
    const float* __restrict__ dist,
    const float* __restrict__ w1, const float* __restrict__ b1,
    const float* __restrict__ w2, const float* __restrict__ b2,
    const int* __restrict__ src, const int* __restrict__ dst)
{
    __shared__ float w1s[96 * 16];
    __shared__ float b1s[16];
    __shared__ float w2s[32];
    __shared__ float b2s[2];
    int tid = threadIdx.x;
    for (int i = tid; i < 96 * 16; i += 256) w1s[i] = w1[i];
    if (tid < 16) b1s[tid] = b1[tid];
    if (tid < 32) w2s[tid] = w2[tid];
    if (tid < 2)  b2s[tid] = b2[tid];
    __syncthreads();

    int e = blockIdx.x * 256 + tid;
    if (e >= EE) return;
    int s = src[e], d = dst[e];

    float h1[16];
#pragma unroll
    for (int j = 0; j < 16; ++j) h1[j] = b1s[j];

    const float4* fs4 = reinterpret_cast<const float4*>(g_featp + s * FPAD);
    const float4* fd4 = reinterpret_cast<const float4*>(g_featp + d * FPAD);

#pragma unroll
    for (int q = 0; q < 12; ++q) {
        float4 f = fs4[q];
        int i0 = q * 4;
#pragma unroll
        for (int j = 0; j < 16; ++j) {
            h1[j] = fmaf(f.x, w1s[(i0 + 0) * 16 + j], h1[j]);
            h1[j] = fmaf(f.y, w1s[(i0 + 1) * 16 + j], h1[j]);
            h1[j] = fmaf(f.z, w1s[(i0 + 2) * 16 + j], h1[j]);
            h1[j] = fmaf(f.w, w1s[(i0 + 3) * 16 + j], h1[j]);
        }
    }
#pragma unroll
    for (int q = 0; q < 12; ++q) {
        float4 f = fd4[q];
        int i0 = 47 + q * 4;
#pragma unroll
        for (int j = 0; j < 16; ++j) {
            h1[j] = fmaf(f.x, w1s[(i0 + 0) * 16 + j], h1[j]);
            h1[j] = fmaf(f.y, w1s[(i0 + 1) * 16 + j], h1[j]);
            h1[j] = fmaf(f.z, w1s[(i0 + 2) * 16 + j], h1[j]);
            h1[j] = fmaf(f.w, w1s[(i0 + 3) * 16 + j], h1[j]);
        }
    }
    float d0 = dist[2 * e], d1 = dist[2 * e + 1];
#pragma unroll
    for (int j = 0; j < 16; ++j) {
        h1[j] = fmaf(d0, w1s[94 * 16 + j], h1[j]);
        h1[j] = fmaf(d1, w1s[95 * 16 + j], h1[j]);
        h1[j] = fsigmoid(h1[j]);
    }
    float c0 = b2s[0], c1 = b2s[1];
#pragma unroll
    for (int j = 0; j < 16; ++j) {
        c0 = fmaf(h1[j], w2s[2 * j],     c0);
        c1 = fmaf(h1[j], w2s[2 * j + 1], c1);
    }
    g_c[2 * e]     = fsigmoid(c0);
    g_c[2 * e + 1] = fsigmoid(c1);
}

// ---------------- main gather kernel: 1 CTA per dst node, 128 threads -------
// thread = (bq = tid>>5, h = tid&31); owns outputs (b, h), b = bq*4 + i.
// w3/b3 slices live in registers; Wt/sb double-buffered (1 barrier/edge).
__global__ void __launch_bounds__(128) k_main(
    const float* __restrict__ state,
    const float* __restrict__ w3, const float* __restrict__ b3,
    const float* __restrict__ weight,
    const int* __restrict__ src,
    float* __restrict__ out)
{
    const int n   = blockIdx.x;
    const int tid = threadIdx.x;
    const int h   = tid & 31;
    const int bq  = tid >> 5;

    __shared__ __align__(16) float Wt[2][32 * WT_STRIDE];  // Wt[h][k] = W[k][h]
    __shared__ __align__(16) float sb[2][16 * 64];         // sb[b][k]; k<32=src, k>=32=dst

    // ---- prologue: w3 slices into registers, packed over k-pairs ----
    ull rap[8], rbp[8], rcp[8];
#pragma unroll
    for (int p = 0; p < 8; ++p) {
        int j0 = (bq * 16 + 2 * p) * 32 + h;
        int j1 = j0 + 32;
        rap[p] = pk(w3[j0],        w3[j1]);
        rbp[p] = pk(w3[2048 + j0], w3[2048 + j1]);
        rcp[p] = pk(b3[j0],        b3[j1]);
    }
    // state[n] (dst half) into both buffers, k = 32..63
    {
        int idx = tid * 4, b = idx >> 5, hh = idx & 31;
        float4 v = *reinterpret_cast<const float4*>(state + n * 512 + idx);
        *reinterpret_cast<float4*>(&sb[0][b * 64 + 32 + hh]) = v;
        *reinterpret_cast<float4*>(&sb[1][b * 64 + 32 + hh]) = v;
    }

    const int rs = g_rowptr[n];
    const int re = g_rowptr[n + 1];

    uint32_t sb_base = (uint32_t)__cvta_generic_to_shared(&sb[0][0]);
    uint32_t wt_base = (uint32_t)__cvta_generic_to_shared(&Wt[0][0]);

    float den[4] = {0.f, 0.f, 0.f, 0.f};
    float num[4] = {0.f, 0.f, 0.f, 0.f};

    for (int ei = rs; ei < re; ++ei) {
        const int buf = (ei - rs) & 1;
        int   e  = g_elist[ei];
        float c0 = g_c[2 * e];
        float c1 = g_c[2 * e + 1];
        int   sn = src[e];

        // stage state[src] into sb[buf] low half (k = 0..31)
        {
            int idx = tid * 4, b = idx >> 5, hh = idx & 31;
            float4 v = *reinterpret_cast<const float4*>(state + sn * 512 + idx);
            *reinterpret_cast<float4*>(&sb[buf][b * 64 + hh]) = v;
        }
        // regenerate W^T slice (k = bq*16..+15, col h) from registers
        {
            ull c0d = pk(c0, c0), c1d = pk(c1, c1);
            float wtmp[16];
#pragma unroll
            for (int p = 0; p < 8; ++p) {
                ull x = rcp[p];
                ffma2(x, c1d, rbp[p]);
                ffma2(x, c0d, rap[p]);
                float xl, xh; upk(xl, xh, x);
                wtmp[2 * p]     = fsigmoid(xl);
                wtmp[2 * p + 1] = fsigmoid(xh);
            }
#pragma unroll
            for (int q = 0; q < 4; ++q)
                *reinterpret_cast<float4*>(&Wt[buf][h * WT_STRIDE + bq * 16 + q * 4]) =
                    make_float4(wtmp[4 * q], wtmp[4 * q + 1], wtmp[4 * q + 2], wtmp[4 * q + 3]);
        }
        __syncthreads();

        // einsum: alpha[b][h] = sum_k sb[b][k] * Wt[h][k]; packed over k-pairs
        uint32_t wrow = wt_base + (uint32_t)(buf * 32 * WT_STRIDE + h * WT_STRIDE) * 4u;
        uint32_t srow = sb_base + (uint32_t)(buf * 16 * 64 + (bq * 4) * 64) * 4u;
        ull accp[4] = {0ull, 0ull, 0ull, 0ull};
#pragma unroll
        for (int kc = 0; kc < 16; ++kc) {
            ull w0, w1; lds2(w0, w1, wrow + kc * 16);
#pragma unroll
            for (int i = 0; i < 4; ++i) {
                ull s0, s1; lds2(s0, s1, srow + i * 256 + kc * 16);
                ffma2(accp[i], s0, w0);
                ffma2(accp[i], s1, w1);
            }
        }
        // leaky_relu -> exp -> accumulate den/num
#pragma unroll
        for (int i = 0; i < 4; ++i) {
            float lo, hi; upk(lo, hi, accp[i]);
            float a = lo + hi;
            a = fmaxf(a, 0.01f * a);           // leaky_relu (slope 0.01)
            float ex = __expf(a);
            den[i] += ex;
            float sval = sb[buf][(bq * 4 + i) * 64 + h];  // state[src][b][h]
            num[i] = fmaf(ex, sval, num[i]);
        }
    }

    float sigw = fsigmoid(weight[0]);
#pragma unroll
    for (int i = 0; i < 4; ++i) {
        float d = (den[i] > 0.f) ? den[i] : 1.f;
        float v = __fdividef(num[i], d) * sigw;
        out[n * 512 + (bq * 4 + i) * 32 + h] = (v > 0.f) ? v : 0.f;
    }
}

// ---------------- launch ----------------
extern "C" void kernel_launch(void* const* d_in, const int* in_sizes, int n_in,
                              void* d_out, int out_size)
{
    const float* state   = (const float*)d_in[0];
    const float* feature = (const float*)d_in[1];
    const float* dist    = (const float*)d_in[2];
    const float* w1      = (const float*)d_in[3];
    const float* b1      = (const float*)d_in[4];
    const float* w2      = (const float*)d_in[5];
    const float* b2      = (const float*)d_in[6];
    const float* w3      = (const float*)d_in[7];
    const float* b3      = (const float*)d_in[8];
    const float* weight  = (const float*)d_in[9];
    const int*   src     = (const int*)d_in[10];
    const int*   dst     = (const int*)d_in[11];
    float* out = (float*)d_out;

    k_prep <<<(NN * FPAD + 255) / 256, 256>>>(feature);
    k_count<<<(EE + 255) / 256, 256>>>(dst);
    k_scan <<<1, 1024>>>();
    k_fill <<<(EE + 255) / 256, 256>>>(dst);
    k_cmlp <<<(EE + 255) / 256, 256>>>(dist, w1, b1, w2, b2, src, dst);
    k_main <<<NN, 128>>>(state, w3, b3, weight, src, out);
}

// round 4
// speedup vs baseline: 1.2505x; 1.0416x over previous
#include <cuda_runtime.h>
#include <cstdint>

// Problem constants (fixed shapes for MetaGAT_34926674051560)
#define NN   5000
#define EE   80000
#define FEAT 47
#define FPAD 48
#define WT_STRIDE 68

using ull = unsigned long long;

// ---------------- device scratch ----------------
__device__ int    g_count [NN];
__device__ int    g_rowptr[NN + 1];
__device__ int    g_cursor[NN];
__device__ int    g_pos   [EE];          // e -> CSR slot
__device__ int    g_srcp  [EE];          // CSR-ordered src node
__device__ float2 g_cp    [EE];          // CSR-ordered (c0, c1)
__device__ float  g_featp [NN * FPAD];

__device__ __forceinline__ float ftanh(float x) {
    float r; asm("tanh.approx.f32 %0, %1;" : "=f"(r) : "f"(x)); return r;
}
__device__ __forceinline__ float fsigmoid(float x) {     // 1 MUFU
    return fmaf(0.5f, ftanh(0.5f * x), 0.5f);
}
__device__ __forceinline__ ull pk(float lo, float hi) {
    ull r; asm("mov.b64 %0, {%1, %2};" : "=l"(r) : "f"(lo), "f"(hi)); return r;
}
__device__ __forceinline__ void upk(float& lo, float& hi, ull v) {
    asm("mov.b64 {%0, %1}, %2;" : "=f"(lo), "=f"(hi) : "l"(v));
}
__device__ __forceinline__ void ffma2(ull& acc, ull a, ull b) {
    asm("fma.rn.f32x2 %0, %1, %2, %0;" : "+l"(acc) : "l"(a), "l"(b));
}
__device__ __forceinline__ void lds2(ull& a, ull& b, uint32_t addr) {
    asm volatile("ld.shared.v2.b64 {%0, %1}, [%2];" : "=l"(a), "=l"(b) : "r"(addr));
}

// ---------------- zero counters + pad features ----------------
__global__ void k_prep(const float* __restrict__ feature) {
    int i = blockIdx.x * blockDim.x + threadIdx.x;
    if (i < NN) g_count[i] = 0;
    if (i < NN * FPAD) {
        int n = i / FPAD, c = i % FPAD;
        g_featp[i] = (c < FEAT) ? feature[n * FEAT + c] : 0.0f;
    }
}

// ---------------- count edges per dst ----------------
__global__ void k_count(const int* __restrict__ dst) {
    int e = blockIdx.x * blockDim.x + threadIdx.x;
    if (e < EE) atomicAdd(&g_count[dst[e]], 1);
}

// ---------------- exclusive scan (shfl-based, 1 block) ----------------
__global__ void k_scan() {
    __shared__ int wtot[32];
    int tid = threadIdx.x, lane = tid & 31, wid = tid >> 5;
    int base = tid * 5;
    int loc[5];
    int run = 0;
#pragma unroll
    for (int t = 0; t < 5; ++t) {
        loc[t] = run;
        int idx = base + t;
        run += (idx < NN) ? g_count[idx] : 0;
    }
    int own = run;
    int inc = run;
#pragma unroll
    for (int off = 1; off < 32; off <<= 1) {
        int v = __shfl_up_sync(0xffffffffu, inc, off);
        if (lane >= off) inc += v;
    }
    if (lane == 31) wtot[wid] = inc;
    __syncthreads();
    if (wid == 0) {
        int v = wtot[lane];
        int s = v;
#pragma unroll
        for (int off = 1; off < 32; off <<= 1) {
            int u = __shfl_up_sync(0xffffffffu, s, off);
            if (lane >= off) s += u;
        }
        wtot[lane] = s - v;
    }
    __syncthreads();
    int excl = wtot[wid] + inc - own;
#pragma unroll
    for (int t = 0; t < 5; ++t) {
        int idx = base + t;
        if (idx < NN) {
            g_rowptr[idx] = excl + loc[t];
            g_cursor[idx] = excl + loc[t];
        }
    }
    if (tid == 1023) g_rowptr[NN] = excl + own;
}

// ---------------- fill CSR slots (record position per edge) ----------------
__global__ void k_fill(const int* __restrict__ dst) {
    int e = blockIdx.x * blockDim.x + threadIdx.x;
    if (e < EE) {
        int idx = atomicAdd(&g_cursor[dst[e]], 1);
        g_pos[e] = idx;
    }
}

// ---------------- per-edge tiny MLP -> CSR-ordered (c0,c1) + src ----------
__global__ void __launch_bounds__(256) k_cmlp(
    const float* __restrict__ dist,
    const float* __restrict__ w1, const float* __restrict__ b1,
    const float* __restrict__ w2, const float* __restrict__ b2,
    const int* __restrict__ src, const int* __restrict__ dst)
{
    __shared__ float w1s[96 * 16];
    __shared__ float b1s[16];
    __shared__ float w2s[32];
    __shared__ float b2s[2];
    int tid = threadIdx.x;
    for (int i = tid; i < 96 * 16; i += 256) w1s[i] = w1[i];
    if (tid < 16) b1s[tid] = b1[tid];
    if (tid < 32) w2s[tid] = w2[tid];
    if (tid < 2)  b2s[tid] = b2[tid];
    __syncthreads();

    int e = blockIdx.x * 256 + tid;
    if (e >= EE) return;
    int s = src[e], d = dst[e];

    float h1[16];
#pragma unroll
    for (int j = 0; j < 16; ++j) h1[j] = b1s[j];

    const float4* fs4 = reinterpret_cast<const float4*>(g_featp + s * FPAD);
    const float4* fd4 = reinterpret_cast<const float4*>(g_featp + d * FPAD);

#pragma unroll
    for (int q = 0; q < 12; ++q) {
        float4 f = fs4[q];
        int i0 = q * 4;
#pragma unroll
        for (int j = 0; j < 16; ++j) {
            h1[j] = fmaf(f.x, w1s[(i0 + 0) * 16 + j], h1[j]);
            h1[j] = fmaf(f.y, w1s[(i0 + 1) * 16 + j], h1[j]);
            h1[j] = fmaf(f.z, w1s[(i0 + 2) * 16 + j], h1[j]);
            h1[j] = fmaf(f.w, w1s[(i0 + 3) * 16 + j], h1[j]);
        }
    }
#pragma unroll
    for (int q = 0; q < 12; ++q) {
        float4 f = fd4[q];
        int i0 = 47 + q * 4;
#pragma unroll
        for (int j = 0; j < 16; ++j) {
            h1[j] = fmaf(f.x, w1s[(i0 + 0) * 16 + j], h1[j]);
            h1[j] = fmaf(f.y, w1s[(i0 + 1) * 16 + j], h1[j]);
            h1[j] = fmaf(f.z, w1s[(i0 + 2) * 16 + j], h1[j]);
            h1[j] = fmaf(f.w, w1s[(i0 + 3) * 16 + j], h1[j]);
        }
    }
    float d0 = dist[2 * e], d1 = dist[2 * e + 1];
#pragma unroll
    for (int j = 0; j < 16; ++j) {
        h1[j] = fmaf(d0, w1s[94 * 16 + j], h1[j]);
        h1[j] = fmaf(d1, w1s[95 * 16 + j], h1[j]);
        h1[j] = fsigmoid(h1[j]);
    }
    float c0 = b2s[0], c1 = b2s[1];
#pragma unroll
    for (int j = 0; j < 16; ++j) {
        c0 = fmaf(h1[j], w2s[2 * j],     c0);
        c1 = fmaf(h1[j], w2s[2 * j + 1], c1);
    }
    int p = g_pos[e];
    g_cp[p]   = make_float2(fsigmoid(c0), fsigmoid(c1));
    g_srcp[p] = s;
}

// ---------------- main gather kernel: 1 CTA per dst node, 128 threads -------
// thread = (bq = tid>>5, h = tid&31); owns outputs (b,h), b = bq*4+i.
// Software-pipelined: edge i+1's (c,src,state) prefetched into registers
// during edge i's regen/einsum. One __syncthreads per edge.
__global__ void __launch_bounds__(128) k_main(
    const float* __restrict__ state,
    const float* __restrict__ w3, const float* __restrict__ b3,
    const float* __restrict__ weight,
    float* __restrict__ out)
{
    const int n   = blockIdx.x;
    const int tid = threadIdx.x;
    const int h   = tid & 31;
    const int bq  = tid >> 5;

    __shared__ __align__(16) float Wt[2][32 * WT_STRIDE];
    __shared__ __align__(16) float sb[2][16 * 64];

    // w3/b3 slices into registers (packed over k-pairs)
    ull rap[8], rbp[8], rcp[8];
#pragma unroll
    for (int p = 0; p < 8; ++p) {
        int j0 = (bq * 16 + 2 * p) * 32 + h;
        int j1 = j0 + 32;
        rap[p] = pk(w3[j0],        w3[j1]);
        rbp[p] = pk(w3[2048 + j0], w3[2048 + j1]);
        rcp[p] = pk(b3[j0],        b3[j1]);
    }
    // state[n] (dst half) into both buffers, k = 32..63
    const int idx = tid * 4, bb = idx >> 5, hh = idx & 31;
    {
        float4 v = *reinterpret_cast<const float4*>(state + n * 512 + idx);
        *reinterpret_cast<float4*>(&sb[0][bb * 64 + 32 + hh]) = v;
        *reinterpret_cast<float4*>(&sb[1][bb * 64 + 32 + hh]) = v;
    }

    const int rs = g_rowptr[n];
    const int re = g_rowptr[n + 1];

    uint32_t sb_base = (uint32_t)__cvta_generic_to_shared(&sb[0][0]);
    uint32_t wt_base = (uint32_t)__cvta_generic_to_shared(&Wt[0][0]);

    float den[4] = {0.f, 0.f, 0.f, 0.f};
    float num[4] = {0.f, 0.f, 0.f, 0.f};

    if (rs < re) {
        // pipeline prologue: load edge rs
        float2 cc = g_cp[rs];
        int    sn = g_srcp[rs];
        float4 sv = *reinterpret_cast<const float4*>(state + sn * 512 + idx);

        for (int ei = rs; ei < re; ++ei) {
            const int buf = (ei - rs) & 1;

            // prefetch next edge's indices (coalesced, L1-resident)
            int ni = (ei + 1 < re) ? (ei + 1) : ei;
            float2 ccn = g_cp[ni];
            int    snn = g_srcp[ni];

            // stage current state[src] into sb[buf] low half
            *reinterpret_cast<float4*>(&sb[buf][bb * 64 + hh]) = sv;

            // regenerate W^T slice (k = bq*16..+15, col h) from registers
            {
                ull c0d = pk(cc.x, cc.x), c1d = pk(cc.y, cc.y);
                float wtmp[16];
#pragma unroll
                for (int p = 0; p < 8; ++p) {
                    ull x = rcp[p];
                    ffma2(x, c1d, rbp[p]);
                    ffma2(x, c0d, rap[p]);
                    float xl, xh; upk(xl, xh, x);
                    wtmp[2 * p]     = fsigmoid(xl);
                    wtmp[2 * p + 1] = fsigmoid(xh);
                }
#pragma unroll
                for (int q = 0; q < 4; ++q)
                    *reinterpret_cast<float4*>(&Wt[buf][h * WT_STRIDE + bq * 16 + q * 4]) =
                        make_float4(wtmp[4 * q], wtmp[4 * q + 1], wtmp[4 * q + 2], wtmp[4 * q + 3]);
            }

            // issue next state gather before the barrier (overlaps sync+einsum)
            float4 svn = *reinterpret_cast<const float4*>(state + snn * 512 + idx);

            __syncthreads();

            // einsum: alpha[b][h] = sum_k sb[b][k] * Wt[h][k] (packed k-pairs)
            uint32_t wrow = wt_base + (uint32_t)(buf * 32 * WT_STRIDE + h * WT_STRIDE) * 4u;
            uint32_t srow = sb_base + (uint32_t)(buf * 16 * 64 + (bq * 4) * 64) * 4u;
            ull accp[4] = {0ull, 0ull, 0ull, 0ull};
#pragma unroll
            for (int kc = 0; kc < 16; ++kc) {
                ull w0, w1; lds2(w0, w1, wrow + kc * 16);
#pragma unroll
                for (int i = 0; i < 4; ++i) {
                    ull s0, s1; lds2(s0, s1, srow + i * 256 + kc * 16);
                    ffma2(accp[i], s0, w0);
                    ffma2(accp[i], s1, w1);
                }
            }
#pragma unroll
            for (int i = 0; i < 4; ++i) {
                float lo, hi; upk(lo, hi, accp[i]);
                float a = lo + hi;
                a = fmaxf(a, 0.01f * a);           // leaky_relu
                float ex = __expf(a);
                den[i] += ex;
                float sval = sb[buf][(bq * 4 + i) * 64 + h];
                num[i] = fmaf(ex, sval, num[i]);
            }

            cc = ccn; sn = snn; sv = svn;
        }
    }

    float sigw = __fdividef(1.0f, 1.0f + __expf(-weight[0]));
#pragma unroll
    for (int i = 0; i < 4; ++i) {
        float d = (den[i] > 0.f) ? den[i] : 1.f;
        float v = __fdividef(num[i], d) * sigw;
        out[n * 512 + (bq * 4 + i) * 32 + h] = (v > 0.f) ? v : 0.f;
    }
}

// ---------------- launch ----------------
extern "C" void kernel_launch(void* const* d_in, const int* in_sizes, int n_in,
                              void* d_out, int out_size)
{
    const float* state   = (const float*)d_in[0];
    const float* feature = (const float*)d_in[1];
    const float* dist    = (const float*)d_in[2];
    const float* w1      = (const float*)d_in[3];
    const float* b1      = (const float*)d_in[4];
    const float* w2      = (const float*)d_in[5];
    const float* b2      = (const float*)d_in[6];
    const float* w3      = (const float*)d_in[7];
    const float* b3      = (const float*)d_in[8];
    const float* weight  = (const float*)d_in[9];
    const int*   src     = (const int*)d_in[10];
    const int*   dst     = (const int*)d_in[11];
    float* out = (float*)d_out;

    k_prep <<<(NN * FPAD + 255) / 256, 256>>>(feature);
    k_count<<<(EE + 255) / 256, 256>>>(dst);
    k_scan <<<1, 1024>>>();
    k_fill <<<(EE + 255) / 256, 256>>>(dst);
    k_cmlp <<<(EE + 255) / 256, 256>>>(dist, w1, b1, w2, b2, src, dst);
    k_main <<<NN, 128>>>(state, w3, b3, weight, out);
}